// round 3
// baseline (speedup 1.0000x reference)
#include <cuda_runtime.h>
#include <math.h>

#define NN 8
#define C_IN 64
#define C_OUT 64
#define HH 128
#define WW 128
#define KK 4

// ---------------- scratch (device globals: no allocations allowed) ----------
__device__ float g_sums[NN][45];                       // 45 class sums per sample
__device__ float g_att[NN][KK];                        // softmax attention
__device__ float g_aggw[NN * C_OUT * C_IN * 9];        // per-sample fused weights (~1.2MB)

// ---------------- kernel 0: zero class-sum scratch ---------------------------
__global__ void zero_sums_kernel() {
    int i = threadIdx.x;
    if (i < NN * 45) ((float*)g_sums)[i] = 0.0f;
}

// ---------------- kernel 1: 45 class sums per sample -------------------------
// One warp per (n, c). Per channel compute: total T, row0 R0, rowLast RL,
// col0 C0, colLast CL, and 4 corners -> 9 spatial-class sums, binned by the
// channel's d-class {0:c=0, 1:c=1, 2:mid, 3:c=62, 4:c=63}.
__global__ void class_sums_kernel(const float* __restrict__ x) {
    int warp = (blockIdx.x * blockDim.x + threadIdx.x) >> 5;
    int lane = threadIdx.x & 31;
    if (warp >= NN * C_IN) return;
    int n = warp / C_IN;
    int c = warp % C_IN;
    const float* p = x + (size_t)(n * C_IN + c) * (HH * WW);

    float T = 0.f, R0 = 0.f, RL = 0.f, Cc0 = 0.f, CcL = 0.f;
    for (int i = lane; i < HH * WW; i += 32) T += p[i];
    for (int i = lane; i < WW; i += 32) {
        R0 += p[i];
        RL += p[(HH - 1) * WW + i];
    }
    for (int h = lane; h < HH; h += 32) {
        Cc0 += p[h * WW];
        CcL += p[h * WW + (WW - 1)];
    }
    #pragma unroll
    for (int o = 16; o; o >>= 1) {
        T   += __shfl_xor_sync(0xffffffffu, T, o);
        R0  += __shfl_xor_sync(0xffffffffu, R0, o);
        RL  += __shfl_xor_sync(0xffffffffu, RL, o);
        Cc0 += __shfl_xor_sync(0xffffffffu, Cc0, o);
        CcL += __shfl_xor_sync(0xffffffffu, CcL, o);
    }
    if (lane == 0) {
        float c00 = p[0];
        float c0L = p[WW - 1];
        float cL0 = p[(HH - 1) * WW];
        float cLL = p[(HH - 1) * WW + (WW - 1)];
        float S[3][3];
        S[0][0] = c00;              S[0][2] = c0L;
        S[0][1] = R0 - c00 - c0L;
        S[2][0] = cL0;              S[2][2] = cLL;
        S[2][1] = RL - cL0 - cLL;
        S[1][0] = Cc0 - c00 - cL0;
        S[1][2] = CcL - c0L - cLL;
        S[1][1] = T - R0 - RL - S[1][0] - S[1][2];
        int cd = (c == 0) ? 0 : (c == 1) ? 1 : (c == C_IN - 2) ? 3 : (c == C_IN - 1) ? 4 : 2;
        float* dst = &g_sums[n][cd * 9];
        #pragma unroll
        for (int i = 0; i < 9; i++) atomicAdd(&dst[i], S[i / 3][i % 3]);
    }
}

// ---------------- kernel 2: logits from class sums + softmax -----------------
__global__ void logits_softmax_kernel(const float* __restrict__ net0_w,
                                      const float* __restrict__ net0_b,
                                      const float* __restrict__ net1_w,
                                      const float* __restrict__ net1_b,
                                      const float* __restrict__ net2_w,
                                      const float* __restrict__ net2_b) {
    __shared__ float lg[NN][KK];
    int t = threadIdx.x;
    if (t < NN * KK) {
        int n = t / KK, k = t % KK;
        float S[5][3][3];
        #pragma unroll
        for (int i = 0; i < 45; i++) ((float*)S)[i] = g_sums[n][i];
        float Stot = 0.f;
        #pragma unroll
        for (int i = 0; i < 45; i++) Stot += ((float*)S)[i];

        // inclusion masks: which classes are covered by tap offset t per dim
        // h/w dims (kernel 3, pad 1): classes {0:first,1:mid,2:last}
        const float mh[3][3]  = {{0,1,1},{1,1,1},{1,1,0}};
        // d dim, net1 (kernel 3, pad 1): classes {0:d0,1:d1,2:mid,3:d62,4:d63}
        const float m1d[3][5] = {{0,1,1,1,1},{1,1,1,1,1},{1,1,1,1,0}};
        // d dim, net2 (kernel 5, pad 2)
        const float m2d[5][5] = {{0,0,1,1,1},{0,1,1,1,1},{1,1,1,1,1},{1,1,1,1,0},{1,1,1,0,0}};
        const float invV = 1.0f / (float)(C_IN * HH * WW);

        float acc = net0_b[k] + net1_b[k] + net2_b[k] + net0_w[k] * Stot * invV;

        float s1 = 0.f;
        for (int td = 0; td < 3; td++) {
            float B[3][3];
            for (int ch = 0; ch < 3; ch++)
                for (int cw = 0; cw < 3; cw++) {
                    float v = 0.f;
                    for (int cd = 0; cd < 5; cd++) v += m1d[td][cd] * S[cd][ch][cw];
                    B[ch][cw] = v;
                }
            for (int th = 0; th < 3; th++)
                for (int tw = 0; tw < 3; tw++) {
                    float box = 0.f;
                    for (int ch = 0; ch < 3; ch++)
                        for (int cw = 0; cw < 3; cw++)
                            box += mh[th][ch] * mh[tw][cw] * B[ch][cw];
                    s1 += net1_w[k * 27 + td * 9 + th * 3 + tw] * box;
                }
        }
        float s2 = 0.f;
        for (int td = 0; td < 5; td++) {
            float B[3][3];
            for (int ch = 0; ch < 3; ch++)
                for (int cw = 0; cw < 3; cw++) {
                    float v = 0.f;
                    for (int cd = 0; cd < 5; cd++) v += m2d[td][cd] * S[cd][ch][cw];
                    B[ch][cw] = v;
                }
            for (int th = 0; th < 3; th++)
                for (int tw = 0; tw < 3; tw++) {
                    float box = 0.f;
                    for (int ch = 0; ch < 3; ch++)
                        for (int cw = 0; cw < 3; cw++)
                            box += mh[th][ch] * mh[tw][cw] * B[ch][cw];
                    s2 += net2_w[k * 45 + td * 9 + th * 3 + tw] * box;
                }
        }
        acc += (s1 + s2) * invV;
        lg[n][k] = acc;
    }
    __syncthreads();
    if (t < NN * KK) {
        int n = t / KK, k = t % KK;
        float m = lg[n][0];
        #pragma unroll
        for (int j = 1; j < KK; j++) m = fmaxf(m, lg[n][j]);
        float sum = 0.f;
        #pragma unroll
        for (int j = 0; j < KK; j++) sum += expf(lg[n][j] - m);
        g_att[n][k] = expf(lg[n][k] - m) / sum;
    }
}

// ---------------- kernel 3: per-sample fused weight = conv_w + sum_k att*w_k -
__global__ void agg_weights_kernel(const float* __restrict__ weight,
                                   const float* __restrict__ conv_w) {
    const int per_n4 = C_OUT * C_IN * 9 / 4;  // 9216 float4 per sample
    int idx = blockIdx.x * blockDim.x + threadIdx.x;
    if (idx >= NN * per_n4) return;
    int n = idx / per_n4;
    int r = idx - n * per_n4;
    float a0 = g_att[n][0], a1 = g_att[n][1], a2 = g_att[n][2], a3 = g_att[n][3];
    float4 base = ((const float4*)conv_w)[r];
    const float4* w4 = (const float4*)weight;
    float4 w0 = w4[0 * per_n4 + r];
    float4 w1 = w4[1 * per_n4 + r];
    float4 w2 = w4[2 * per_n4 + r];
    float4 w3 = w4[3 * per_n4 + r];
    float4 o;
    o.x = base.x + a0 * w0.x + a1 * w1.x + a2 * w2.x + a3 * w3.x;
    o.y = base.y + a0 * w0.y + a1 * w1.y + a2 * w2.y + a3 * w3.y;
    o.z = base.z + a0 * w0.z + a1 * w1.z + a2 * w2.z + a3 * w3.z;
    o.w = base.w + a0 * w0.w + a1 * w1.w + a2 * w2.w + a3 * w3.w;
    ((float4*)g_aggw)[(size_t)n * per_n4 + r] = o;
}

// ---------------- kernel 4: fused direct conv2d (3x3, pad1) + bias -----------
// Block tile: 32 co x 16 h x 32 w, one sample. Loop C_IN in chunks of 8.
// Threads: 256 = 4(tc: 8 co each) x 8(th: 2 h each) x 8(tw: 4 w each).
// Weight reads are warp-uniform (broadcast); x reuse from SMEM.
__global__ __launch_bounds__(256, 2)
void conv_fused_kernel(const float* __restrict__ x,
                       const float* __restrict__ conv_b,
                       float* __restrict__ out) {
    const int CI_C = 8;
    __shared__ float xs[CI_C][18][36];
    __shared__ float wsm[32][CI_C][9];

    int w0 = blockIdx.x * 32;
    int h0 = blockIdx.y * 16;
    int n   = blockIdx.z >> 1;
    int co0 = (blockIdx.z & 1) * 32;

    int tid = threadIdx.x;
    int tc = tid >> 6;         // 0..3
    int th = (tid >> 3) & 7;   // 0..7
    int tw = tid & 7;          // 0..7

    float acc[8][2][4];
    #pragma unroll
    for (int j = 0; j < 8; j++)
        #pragma unroll
        for (int r = 0; r < 2; r++)
            #pragma unroll
            for (int c = 0; c < 4; c++) acc[j][r][c] = 0.f;

    const float* xn = x + (size_t)n * C_IN * HH * WW;
    const float* wn = g_aggw + (size_t)n * C_OUT * C_IN * 9;

    for (int cib = 0; cib < C_IN; cib += CI_C) {
        // --- load x tile with halo (18 x 34), zero padding outside ---
        for (int i = tid; i < CI_C * 18 * 34; i += 256) {
            int ci = i / (18 * 34);
            int rem = i - ci * (18 * 34);
            int rr = rem / 34;
            int cc = rem - rr * 34;
            int gh = h0 - 1 + rr;
            int gw = w0 - 1 + cc;
            float v = 0.f;
            if ((unsigned)gh < (unsigned)HH && (unsigned)gw < (unsigned)WW)
                v = xn[(size_t)(cib + ci) * (HH * WW) + gh * WW + gw];
            xs[ci][rr][cc] = v;
        }
        // --- load weight chunk ---
        for (int i = tid; i < 32 * CI_C * 9; i += 256) {
            int co = i / (CI_C * 9);
            int rem = i - co * (CI_C * 9);
            int ci = rem / 9;
            int kk = rem - ci * 9;
            wsm[co][ci][kk] = wn[(size_t)(co0 + co) * (C_IN * 9) + (cib + ci) * 9 + kk];
        }
        __syncthreads();

        #pragma unroll
        for (int ci = 0; ci < CI_C; ci++) {
            #pragma unroll
            for (int kh = 0; kh < 3; kh++) {
                float xr[2][6];
                #pragma unroll
                for (int r = 0; r < 2; r++)
                    #pragma unroll
                    for (int c = 0; c < 6; c++)
                        xr[r][c] = xs[ci][th * 2 + r + kh][tw * 4 + c];
                #pragma unroll
                for (int kw = 0; kw < 3; kw++) {
                    #pragma unroll
                    for (int j = 0; j < 8; j++) {
                        float wv = wsm[tc * 8 + j][ci][kh * 3 + kw];
                        #pragma unroll
                        for (int r = 0; r < 2; r++)
                            #pragma unroll
                            for (int c = 0; c < 4; c++)
                                acc[j][r][c] = fmaf(xr[r][c + kw], wv, acc[j][r][c]);
                    }
                }
            }
        }
        __syncthreads();
    }

    // --- epilogue: add bias (the residual conv's bias), vectorized store ---
    #pragma unroll
    for (int j = 0; j < 8; j++) {
        int co = co0 + tc * 8 + j;
        float b = conv_b[co];
        #pragma unroll
        for (int r = 0; r < 2; r++) {
            int h = h0 + th * 2 + r;
            int w = w0 + tw * 4;
            float4 v;
            v.x = acc[j][r][0] + b;
            v.y = acc[j][r][1] + b;
            v.z = acc[j][r][2] + b;
            v.w = acc[j][r][3] + b;
            *(float4*)&out[((size_t)(n * C_OUT + co) * HH + h) * WW + w] = v;
        }
    }
}

// ---------------- launch ------------------------------------------------------
extern "C" void kernel_launch(void* const* d_in, const int* in_sizes, int n_in,
                              void* d_out, int out_size) {
    const float* x      = (const float*)d_in[0];
    const float* weight = (const float*)d_in[1];
    const float* conv_w = (const float*)d_in[2];
    const float* conv_b = (const float*)d_in[3];
    const float* net0_w = (const float*)d_in[4];
    const float* net0_b = (const float*)d_in[5];
    const float* net1_w = (const float*)d_in[6];
    const float* net1_b = (const float*)d_in[7];
    const float* net2_w = (const float*)d_in[8];
    const float* net2_b = (const float*)d_in[9];
    float* out = (float*)d_out;

    zero_sums_kernel<<<1, 512>>>();
    class_sums_kernel<<<(NN * C_IN * 32) / 256, 256>>>(x);
    logits_softmax_kernel<<<1, 32>>>(net0_w, net0_b, net1_w, net1_b, net2_w, net2_b);
    agg_weights_kernel<<<(NN * C_OUT * C_IN * 9 / 4 + 255) / 256, 256>>>(weight, conv_w);
    conv_fused_kernel<<<dim3(WW / 32, HH / 16, NN * 2), 256>>>(x, conv_b, out);
}